// round 2
// baseline (speedup 1.0000x reference)
#include <cuda_runtime.h>
#include <math.h>

// Problem shape (fixed by dataset): X is (65536, 512) fp32 row-major.
#define CDIM 512
#define BDIM 65536
#define NB1  1024          // pass-1 blocks (64 rows each)
#define R1   (BDIM / NB1)  // 64
#define NB3  2048          // pass-3 blocks (32 rows each)
#define R3   (BDIM / NB3)  // 32

// Static device scratch (no allocations allowed).
__device__ __align__(16) float g_sumP[NB1][CDIM];
__device__ __align__(16) float g_maxP[NB1][CDIM];
__device__ __align__(16) float g_minP[NB1][CDIM];
__device__ __align__(16) float g_mean[CDIM];
__device__ __align__(16) float g_u[CDIM];
__device__ __align__(16) float g_dev[CDIM];
__device__ __align__(16) float g_c1[CDIM];
__device__ __align__(16) float g_c2[CDIM];
__device__ __align__(16) float g_wc[CDIM];
__device__ float g_sn1;

// ---------------------------------------------------------------------------
// Pass 1: per-column partial sum / max / min. Block b covers rows
// [b*R1, (b+1)*R1); 128 threads each own 4 consecutive columns (float4).
// Loads are fully coalesced (block reads a contiguous 128 KiB chunk).
// ---------------------------------------------------------------------------
__global__ void k_pass1(const float* __restrict__ X) {
    const int t = threadIdx.x;      // 0..127
    const int b = blockIdx.x;       // 0..NB1-1
    const float4* Xp = reinterpret_cast<const float4*>(X);
    size_t base = (size_t)b * R1 * (CDIM / 4) + t;

    float4 s  = make_float4(0.f, 0.f, 0.f, 0.f);
    float4 mx = make_float4(-INFINITY, -INFINITY, -INFINITY, -INFINITY);
    float4 mn = make_float4( INFINITY,  INFINITY,  INFINITY,  INFINITY);

#pragma unroll 8
    for (int r = 0; r < R1; r++) {
        float4 v = Xp[base + (size_t)r * (CDIM / 4)];
        s.x += v.x; s.y += v.y; s.z += v.z; s.w += v.w;
        mx.x = fmaxf(mx.x, v.x); mx.y = fmaxf(mx.y, v.y);
        mx.z = fmaxf(mx.z, v.z); mx.w = fmaxf(mx.w, v.w);
        mn.x = fminf(mn.x, v.x); mn.y = fminf(mn.y, v.y);
        mn.z = fminf(mn.z, v.z); mn.w = fminf(mn.w, v.w);
    }
    reinterpret_cast<float4*>(g_sumP[b])[t] = s;
    reinterpret_cast<float4*>(g_maxP[b])[t] = mx;
    reinterpret_cast<float4*>(g_minP[b])[t] = mn;
}

// ---------------------------------------------------------------------------
// Stage 2a: reduce the NB1 partials per column (deterministic fixed-order
// tree). Block jb handles 4 columns. Emits mean[j], u[j], dev[j] where
// dev[j] = max_i |x[i,j] - mean[j]| = max(max-mean, mean-min).
// ---------------------------------------------------------------------------
__global__ void k_stage2a() {
    const int t  = threadIdx.x;   // 0..127
    const int jb = blockIdx.x;    // 0..127 (4 cols each)

    float4 s  = make_float4(0.f, 0.f, 0.f, 0.f);
    float4 mx = make_float4(-INFINITY, -INFINITY, -INFINITY, -INFINITY);
    float4 mn = make_float4( INFINITY,  INFINITY,  INFINITY,  INFINITY);

    for (int r = t; r < NB1; r += 128) {
        float4 vs = *reinterpret_cast<const float4*>(&g_sumP[r][jb * 4]);
        float4 va = *reinterpret_cast<const float4*>(&g_maxP[r][jb * 4]);
        float4 vi = *reinterpret_cast<const float4*>(&g_minP[r][jb * 4]);
        s.x += vs.x; s.y += vs.y; s.z += vs.z; s.w += vs.w;
        mx.x = fmaxf(mx.x, va.x); mx.y = fmaxf(mx.y, va.y);
        mx.z = fmaxf(mx.z, va.z); mx.w = fmaxf(mx.w, va.w);
        mn.x = fminf(mn.x, vi.x); mn.y = fminf(mn.y, vi.y);
        mn.z = fminf(mn.z, vi.z); mn.w = fminf(mn.w, vi.w);
    }

    __shared__ float4 shS[128], shA[128], shI[128];
    shS[t] = s; shA[t] = mx; shI[t] = mn;
    __syncthreads();
    for (int off = 64; off > 0; off >>= 1) {
        if (t < off) {
            float4 a = shS[t], b2 = shS[t + off];
            a.x += b2.x; a.y += b2.y; a.z += b2.z; a.w += b2.w;
            shS[t] = a;
            float4 c = shA[t], d = shA[t + off];
            c.x = fmaxf(c.x, d.x); c.y = fmaxf(c.y, d.y);
            c.z = fmaxf(c.z, d.z); c.w = fmaxf(c.w, d.w);
            shA[t] = c;
            float4 e = shI[t], f = shI[t + off];
            e.x = fminf(e.x, f.x); e.y = fminf(e.y, f.y);
            e.z = fminf(e.z, f.z); e.w = fminf(e.w, f.w);
            shI[t] = e;
        }
        __syncthreads();
    }

    if (t == 0) {
        const float cb = (float)(1.0 / sqrt(2.0 * log((double)BDIM)));
        const float* ps = reinterpret_cast<const float*>(&shS[0]);
        const float* pa = reinterpret_cast<const float*>(&shA[0]);
        const float* pi = reinterpret_cast<const float*>(&shI[0]);
        for (int c = 0; c < 4; c++) {
            float mean = ps[c] * (1.0f / (float)BDIM);  // /2^16, exact scaling
            float uv   = cb * (pa[c] - pi[c]);
            float dev  = fmaxf(pa[c] - mean, mean - pi[c]);
            g_mean[jb * 4 + c] = mean;
            g_u[jb * 4 + c]    = uv;
            g_dev[jb * 4 + c]  = dev;
        }
    }
}

// ---------------------------------------------------------------------------
// Stage 2b: global scalars (dmax/wmax/bmax -> SN1/SN2/SN3) and per-column
// fused constants c1, c2 and clamped signed ww (g_wc). One block, 512 thr.
// ---------------------------------------------------------------------------
__device__ __forceinline__ float pow2_floor_log2(float v) {
    // replicates exp2(floor(log2(floor(v)))) including the v<1 -> 0 edge
    float f = floorf(v);
    if (f < 1.0f) return 0.0f;
    return ldexpf(1.0f, ilogbf(f));
}

__global__ void k_stage2b(const float* __restrict__ w,
                          const float* __restrict__ bia) {
    const int j = threadIdx.x;  // 0..511 (= column = w-group index)
    float dev = g_dev[j];
    float uv  = g_u[j];
    float wv  = w[j];
    float bv  = bia[j];

    __shared__ float sh[CDIM];
    __shared__ float s_dmax, s_wmax, s_sn1, s_sn2, s_sn3;

    // dmax = max over cols of max(|q|_col, |u|_col)
    sh[j] = fmaxf(dev, fabsf(uv));
    __syncthreads();
    for (int off = 256; off > 0; off >>= 1) {
        if (j < off) sh[j] = fmaxf(sh[j], sh[j + off]);
        __syncthreads();
    }
    if (j == 0) s_dmax = (sh[0] == 0.f) ? 1.f : sh[0];
    __syncthreads();

    sh[j] = fabsf(wv);
    __syncthreads();
    for (int off = 256; off > 0; off >>= 1) {
        if (j < off) sh[j] = fmaxf(sh[j], sh[j + off]);
        __syncthreads();
    }
    if (j == 0) s_wmax = (sh[0] == 0.f) ? 1.f : sh[0];
    __syncthreads();

    sh[j] = fabsf(bv);
    __syncthreads();
    for (int off = 256; off > 0; off >>= 1) {
        if (j < off) sh[j] = fmaxf(sh[j], sh[j + off]);
        __syncthreads();
    }
    if (j == 0) {
        float bmax = (sh[0] == 0.f) ? 1.f : sh[0];
        s_sn1 = pow2_floor_log2(32.0f / s_dmax);
        s_sn2 = pow2_floor_log2(32.0f / s_wmax);
        s_sn3 = pow2_floor_log2(32.0f / bmax);
        g_sn1 = s_sn1;
    }
    __syncthreads();

    const float SN1 = s_sn1, SN2 = s_sn2, SN3 = s_sn3;

    int uu = (int)(uv * SN1);       // trunc toward zero == astype(int32)
    int ww = (int)(wv * SN2);
    int bq = (int)(bv * SN3);

    int iu = min(abs(uu), 64);
    int ib = min(abs(bq), 64);
    float sgu = (uv > 0.f) ? 1.f : ((uv < 0.f) ? -1.f : 0.f);
    float sgb = (bv > 0.f) ? 1.f : ((bv < 0.f) ? -1.f : 0.f);
    float x8 = (float)(iu * ib) * sgu * sgb;

    float ssv = (float)uu * SN2 * SN3;
    g_c1[j] = SN3 / ssv;            // x7 coefficient
    g_c2[j] = x8 * SN2 / ssv;       // additive term

    int wc = max(-64, min(64, ww)); // signed-clamp == sign*clip(|.|,64)
    g_wc[j] = (float)wc;
}

// ---------------------------------------------------------------------------
// Pass 3: elementwise output. Block b covers rows [b*R3, b*R3+R3) — all in
// one w-group g = row>>7 (ww index from the repeat_interleave pairing:
// k//B == row>>7 exactly, since (row&127)*512+col <= 65535 < B).
// out = clamp((int)((x-mean)*SN1), +-64) * (wc[g]*c1[j]) + c2[j]
// 256 threads: thread t handles column 4*(t&127).., row-parity t>>7.
// Per-column constants in registers; two rows in flight per iteration.
// ---------------------------------------------------------------------------
__global__ void k_pass3(const float* __restrict__ X, float* __restrict__ O) {
    const int tc = threadIdx.x & 127;   // column group 0..127
    const int tr = threadIdx.x >> 7;    // row parity 0..1
    const int b = blockIdx.x;
    const int row0 = b * R3;
    const int g = row0 >> 7;            // 32-row blocks never straddle groups

    float4 m  = reinterpret_cast<const float4*>(g_mean)[tc];
    float4 c1 = reinterpret_cast<const float4*>(g_c1)[tc];
    float4 c2 = reinterpret_cast<const float4*>(g_c2)[tc];
    const float wg  = g_wc[g];
    const float sn1 = g_sn1;
    float4 e1;
    e1.x = wg * c1.x; e1.y = wg * c1.y; e1.z = wg * c1.z; e1.w = wg * c1.w;

    const float4* Xp = reinterpret_cast<const float4*>(X);
    float4* Op = reinterpret_cast<float4*>(O);
    size_t base = (size_t)(row0 + tr) * (CDIM / 4) + tc;

#pragma unroll 8
    for (int r = 0; r < R3; r += 2) {
        float4 v = Xp[base + (size_t)r * (CDIM / 4)];
        float4 o;
        {
            int q = (int)((v.x - m.x) * sn1);
            q = max(-64, min(64, q));
            o.x = (float)q * e1.x + c2.x;
        }
        {
            int q = (int)((v.y - m.y) * sn1);
            q = max(-64, min(64, q));
            o.y = (float)q * e1.y + c2.y;
        }
        {
            int q = (int)((v.z - m.z) * sn1);
            q = max(-64, min(64, q));
            o.z = (float)q * e1.z + c2.z;
        }
        {
            int q = (int)((v.w - m.w) * sn1);
            q = max(-64, min(64, q));
            o.w = (float)q * e1.w + c2.w;
        }
        Op[base + (size_t)r * (CDIM / 4)] = o;
    }
}

// ---------------------------------------------------------------------------
extern "C" void kernel_launch(void* const* d_in, const int* in_sizes, int n_in,
                              void* d_out, int out_size) {
    const float* X  = (const float*)d_in[0];   // (65536, 512)
    const float* w  = (const float*)d_in[1];   // (512,)
    const float* bi = (const float*)d_in[2];   // (512,)
    float* O = (float*)d_out;

    k_pass1<<<NB1, 128>>>(X);
    k_stage2a<<<CDIM / 4, 128>>>();
    k_stage2b<<<1, CDIM>>>(w, bi);
    k_pass3<<<NB3, 256>>>(X, O);
}